// round 3
// baseline (speedup 1.0000x reference)
#include <cuda_runtime.h>
#include <math.h>

#define H        64
#define NZ       120
#define NLAYERS  4
#define DIMH     256
#define DIMG     65536
#define GRID     148
#define TPB      512

// Scratch (no allocations allowed)
__device__ int   d_part[GRID * NZ];    // per-block histogram partials
__device__ float d_wtab[NZ * H];       // count-weighted post-layer table
__device__ float d_gbuf[DIMG];         // unsymmetrized g
__device__ float d_hbuf[DIMH];         // unsymmetrized h
__device__ float d_sinkf;              // prefetch elision guard

// Sense-reversing global barrier. Counter self-resets each use; generation
// monotonically increases (wrap-safe), so graph replays are deterministic.
__device__ unsigned d_bar_cnt = 0;
__device__ unsigned d_bar_gen = 0;

__device__ __forceinline__ void gsync() {
    __syncthreads();
    if (threadIdx.x == 0) {
        unsigned g = atomicAdd(&d_bar_gen, 0u);
        __threadfence();
        if (atomicAdd(&d_bar_cnt, 1u) == GRID - 1) {
            d_bar_cnt = 0;
            __threadfence();
            atomicAdd(&d_bar_gen, 1u);          // release
        } else {
            while (atomicAdd(&d_bar_gen, 0u) == g) { }
        }
        __threadfence();
    }
    __syncthreads();
}

__global__ void __launch_bounds__(TPB, 1)
fused_kernel(const int* __restrict__ Z, int n,
             const float* __restrict__ embed, const float* __restrict__ W_tp,
             const float* __restrict__ w_h,   const float* __restrict__ b_h,
             const float* __restrict__ w_g,   const float* __restrict__ b_g,
             float* __restrict__ out) {
    __shared__ int   sh[NZ];
    __shared__ float xs[H];
    __shared__ float gf[H];
    __shared__ float red2[TPB];
    __shared__ float scnt;

    const int t    = threadIdx.x;
    const int bid  = blockIdx.x;
    const int gtid = bid * TPB + t;
    const int nthr = GRID * TPB;

    // ---------------- Phase 1: histogram + w_g L2 prefetch -----------------
    for (int i = t; i < NZ; i += TPB) sh[i] = 0;
    __syncthreads();

    // dtype sniff: Z declared int64 in the reference; with x64 off it lands
    // int32. int64 little-endian data (<120) has every odd word == 0.
    bool is64 = true;
    #pragma unroll
    for (int i = 0; i < 32; ++i)
        if (Z[2 * i + 1] != 0) { is64 = false; break; }

    const int4* __restrict__ Z4 = (const int4*)Z;
    if (!is64) {
        const int n4 = n >> 2;
        for (int i = gtid; i < n4; i += nthr) {
            int4 v = Z4[i];
            atomicAdd(&sh[v.x], 1); atomicAdd(&sh[v.y], 1);
            atomicAdd(&sh[v.z], 1); atomicAdd(&sh[v.w], 1);
        }
    } else {
        const int n2 = n >> 1;                  // int4 covers 2 int64 elems
        for (int i = gtid; i < n2; i += nthr) {
            int4 v = Z4[i];
            atomicAdd(&sh[v.x], 1); atomicAdd(&sh[v.z], 1);
        }
    }
    __syncthreads();
    for (int i = t; i < NZ; i += TPB) d_part[bid * NZ + i] = sh[i];

    // Stream w_g into L2 (bypass L1) so the phase-3 matvec is L2-resident.
    {
        const float4* __restrict__ w4 = (const float4*)w_g;
        const int nw4 = (H * DIMG) / 4;         // 1,048,576 float4
        float acc = 0.f;
        for (int i = gtid; i < nw4; i += nthr) {
            float4 v = __ldcg(&w4[i]);
            acc += v.x + v.y + v.z + v.w;
        }
        if (acc == -1.0f) d_sinkf = acc;        // keeps the loads alive
    }

    gsync();

    // ---------------- Phase 2: 120-row table through 4 layers --------------
    // Blocks 0..119: threads 0..63 run the layers; warp 2 sums counts.
    if (bid < NZ && t < H) xs[t] = embed[bid * H + t];
    if (bid < NZ && t >= 64 && t < 96) {
        float c = 0.f;
        for (int b = t - 64; b < GRID; b += 32) c += (float)d_part[b * NZ + bid];
        #pragma unroll
        for (int o = 16; o; o >>= 1) c += __shfl_down_sync(0xffffffffu, c, o);
        if (t == 64) scnt = c;
    }
    __syncthreads();

    #pragma unroll
    for (int l = 0; l < NLAYERS; ++l) {
        float a = 0.f;
        if (bid < NZ && t < H) {
            const float* __restrict__ W = W_tp + l * H * H;
            #pragma unroll
            for (int k = 0; k < H; ++k)
                a = fmaf(xs[k], W[k * H + t], a);
            a *= 0.125f;                         // INV_SQRT_H = 1/sqrt(64)
            a = a / (1.f + expf(-a));            // silu
        }
        __syncthreads();
        if (bid < NZ && t < H) xs[t] = a;
        __syncthreads();
    }
    if (bid < NZ && t < H) d_wtab[bid * H + t] = scnt * xs[t];

    gsync();

    // ---------------- Phase 3: g_feat reduce + matvecs ---------------------
    {   // g_feat[j] = sum_z d_wtab[z][j]; 8 strips of 15 (L2-resident reads)
        const int j = t & 63, p = t >> 6;
        float s = 0.f;
        #pragma unroll
        for (int z = p * 15; z < p * 15 + 15; ++z) s += d_wtab[z * H + j];
        red2[t] = s;
        __syncthreads();
        if (t < 64) {
            float g2 = 0.f;
            #pragma unroll
            for (int q = 0; q < 8; ++q) g2 += red2[t + 64 * q];
            gf[t] = g2;
        }
        __syncthreads();
    }
    if (gtid < DIMG) {
        float acc = b_g[gtid];
        #pragma unroll
        for (int k = 0; k < H; ++k)
            acc = fmaf(gf[k], __ldcg(&w_g[k * DIMG + gtid]), acc);  // L2 hit
        d_gbuf[gtid] = acc;
    } else if (gtid < DIMG + DIMH) {
        const int i2 = gtid - DIMG;
        float acc = b_h[i2];
        #pragma unroll
        for (int k = 0; k < H; ++k)
            acc = fmaf(gf[k], w_h[k * DIMH + i2], acc);
        d_hbuf[i2] = acc;
    }

    gsync();

    // ---------------- Phase 4: 8-fold symmetrization -----------------------
    for (int idx = gtid; idx < DIMG; idx += nthr) {
        const int a = idx >> 12, b = (idx >> 8) & 15,
                  c = (idx >> 4) & 15, d = idx & 15;
#define GIDX(x, y, zz, w) d_gbuf[((x) << 12) | ((y) << 8) | ((zz) << 4) | (w)]
        float s = GIDX(a, b, c, d) + GIDX(b, a, c, d)
                + GIDX(a, b, d, c) + GIDX(b, a, d, c)
                + GIDX(c, d, a, b) + GIDX(d, c, a, b)
                + GIDX(c, d, b, a) + GIDX(d, c, b, a);
#undef GIDX
        out[256 + idx] = 0.125f * s;
    }
    if (gtid < DIMH) {
        const int i2 = gtid >> 4, j2 = gtid & 15;
        out[gtid] = 0.5f * (d_hbuf[gtid] + d_hbuf[j2 * 16 + i2]);
    }
}

// Inputs (metadata order): Z, pos, ghost, embed, W_tp, w_h, b_h, w_g, b_g.
// pos and ghost are dead code in the reference -- never touched.
extern "C" void kernel_launch(void* const* d_in, const int* in_sizes, int n_in,
                              void* d_out, int out_size) {
    const int*   Z     = (const int*)d_in[0];
    const float* embed = (const float*)d_in[3];
    const float* W_tp  = (const float*)d_in[4];
    const float* w_h   = (const float*)d_in[5];
    const float* b_h   = (const float*)d_in[6];
    const float* w_g   = (const float*)d_in[7];
    const float* b_g   = (const float*)d_in[8];
    float* out = (float*)d_out;
    const int n = in_sizes[0];

    fused_kernel<<<GRID, TPB>>>(Z, n, embed, W_tp, w_h, b_h, w_g, b_g, out);
}

// round 6
// speedup vs baseline: 1.2810x; 1.2810x over previous
#include <cuda_runtime.h>
#include <math.h>

#define H        64
#define NZ       120
#define NLAYERS  4
#define DIMH     256
#define DIMG     65536

#define TB_BLKS  120            // table blocks in k1
#define HB_BLKS  64             // histogram blocks in k1
#define PF_BLKS  1024           // prefetch blocks in k1
#define GRID1    (TB_BLKS + HB_BLKS + PF_BLKS)

// Scratch (no allocations allowed)
__device__ int   d_part[HB_BLKS * NZ];  // per-block histogram partials
__device__ float d_ftab[NZ * H];        // UNWEIGHTED post-layer table f_z
__device__ float d_gbuf[DIMG];          // unsymmetrized g
__device__ float d_sinkf;               // prefetch elision guard

// ---------------------------------------------------------------------------
// k1: three INDEPENDENT jobs in one wide launch.
//   blocks [0,120):    f_z table through 4 layers (needs embed/W_tp only)
//   blocks [120,184):  histogram of Z (shared int atomics, per-block partials)
//   blocks [184,1208): stream w_g into L2 (262144 thr x 4 float4, MLP=4)
// ---------------------------------------------------------------------------
__global__ void __launch_bounds__(256)
k1(const int* __restrict__ Z, int n,
   const float* __restrict__ embed, const float* __restrict__ W_tp,
   const float* __restrict__ w_g) {
    const int t   = threadIdx.x;
    const int bid = blockIdx.x;

    if (bid < TB_BLKS) {
        // ---- layer table (threads 0..63 active; all hit the syncs) ----
        __shared__ float xs[H];
        const int z = bid;
        if (t < H) xs[t] = embed[z * H + t];
        __syncthreads();
        #pragma unroll
        for (int l = 0; l < NLAYERS; ++l) {
            float a = 0.f;
            if (t < H) {
                const float* __restrict__ W = W_tp + l * H * H;
                #pragma unroll
                for (int k = 0; k < H; ++k)
                    a = fmaf(xs[k], W[k * H + t], a);
                a *= 0.125f;                    // INV_SQRT_H = 1/sqrt(64)
                a = a / (1.f + expf(-a));       // silu
            }
            __syncthreads();
            if (t < H) xs[t] = a;
            __syncthreads();
        }
        if (t < H) d_ftab[z * H + t] = xs[t];
    } else if (bid < TB_BLKS + HB_BLKS) {
        // ---- histogram ----
        __shared__ int sh[NZ];
        const int hb = bid - TB_BLKS;
        for (int i = t; i < NZ; i += 256) sh[i] = 0;
        __syncthreads();

        // dtype sniff: Z declared int64 in the reference; with x64 off it
        // lands int32. int64 LE data (<120) has every odd word == 0.
        bool is64 = true;
        #pragma unroll
        for (int i = 0; i < 32; ++i)
            if (Z[2 * i + 1] != 0) { is64 = false; break; }

        const int4* __restrict__ Z4 = (const int4*)Z;
        const int tid = hb * 256 + t, nthr = HB_BLKS * 256;
        if (!is64) {
            const int n4 = n >> 2;
            #pragma unroll 2
            for (int i = tid; i < n4; i += nthr) {
                int4 v = Z4[i];
                atomicAdd(&sh[v.x], 1); atomicAdd(&sh[v.y], 1);
                atomicAdd(&sh[v.z], 1); atomicAdd(&sh[v.w], 1);
            }
        } else {
            const int n2 = n >> 1;              // int4 covers 2 int64 elems
            #pragma unroll 2
            for (int i = tid; i < n2; i += nthr) {
                int4 v = Z4[i];
                atomicAdd(&sh[v.x], 1); atomicAdd(&sh[v.z], 1);
            }
        }
        __syncthreads();
        for (int i = t; i < NZ; i += 256) d_part[hb * NZ + i] = sh[i];
    } else {
        // ---- w_g -> L2 prefetch: exactly 4 independent float4 per thread ----
        const int pid = bid - TB_BLKS - HB_BLKS;        // [0,1024)
        const float4* __restrict__ w4 = (const float4*)w_g;
        const int base = pid * 1024;                    // 4 chunks of 256
        float4 a = __ldcg(&w4[base + t]);
        float4 b = __ldcg(&w4[base + 256 + t]);
        float4 c = __ldcg(&w4[base + 512 + t]);
        float4 d = __ldcg(&w4[base + 768 + t]);
        float s = a.x + a.y + a.z + a.w + b.x + b.y + b.z + b.w
                + c.x + c.y + c.z + c.w + d.x + d.y + d.z + d.w;
        if (s == -1.0f) d_sinkf = s;            // keeps the loads alive
    }
}

// ---------------------------------------------------------------------------
// k3 (grid 257): every block first redundantly reduces gf from the L2-hot
// d_part/d_ftab (saves a dedicated reduction launch). Then blocks 0..255
// compute g = gf @ w_g + b_g (w_g L2-resident: prefetched in k1 + persistent
// across graph replays); block 256 does the h matvec + h symmetrization.
// ---------------------------------------------------------------------------
__global__ void __launch_bounds__(256)
k3(const float* __restrict__ w_g, const float* __restrict__ b_g,
   const float* __restrict__ w_h, const float* __restrict__ b_h,
   float* __restrict__ out) {
    __shared__ float scnt[NZ];
    __shared__ float gf[H];
    __shared__ float red[DIMH];
    const int t = threadIdx.x;

    // counts: thread z sums its 64 partials (independent L2 loads, MLP~64)
    if (t < NZ) {
        float c = 0.f;
        #pragma unroll
        for (int b = 0; b < HB_BLKS; ++b)
            c += (float)d_part[b * NZ + t];
        scnt[t] = c;
    }
    __syncthreads();

    // gf[j] = sum_z scnt[z] * f_z[j]; 4 strips of 30 z's per feature j
    {
        const int j = t & 63, p = t >> 6;
        float s = 0.f;
        #pragma unroll
        for (int z = p * 30; z < p * 30 + 30; ++z)
            s = fmaf(scnt[z], d_ftab[z * H + j], s);
        red[t] = s;
        __syncthreads();
        if (t < H) gf[t] = red[t] + red[t + 64] + red[t + 128] + red[t + 192];
        __syncthreads();
    }

    if (blockIdx.x < 256) {
        const int i = blockIdx.x * 256 + t;
        float acc = b_g[i];
        #pragma unroll
        for (int k = 0; k < H; ++k)
            acc = fmaf(gf[k], __ldcg(&w_g[k * DIMG + i]), acc);   // L2 hit
        d_gbuf[i] = acc;
    } else {
        float acc = b_h[t];
        #pragma unroll
        for (int k = 0; k < H; ++k)
            acc = fmaf(gf[k], w_h[k * DIMH + t], acc);
        red[t] = acc;
        __syncthreads();
        const int i = t >> 4, j = t & 15;
        out[t] = 0.5f * (red[i * 16 + j] + red[j * 16 + i]);
    }
}

// ---------------------------------------------------------------------------
// k4: 8-fold permutation symmetrization of g (d_gbuf is L2-hot, 256 KB).
// ---------------------------------------------------------------------------
__global__ void __launch_bounds__(256)
k4(float* __restrict__ out) {
    const int idx = blockIdx.x * 256 + threadIdx.x;
    const int a = idx >> 12, b = (idx >> 8) & 15, c = (idx >> 4) & 15, d = idx & 15;
#define GIDX(x, y, zz, w) d_gbuf[((x) << 12) | ((y) << 8) | ((zz) << 4) | (w)]
    float s = GIDX(a, b, c, d) + GIDX(b, a, c, d)
            + GIDX(a, b, d, c) + GIDX(b, a, d, c)
            + GIDX(c, d, a, b) + GIDX(d, c, a, b)
            + GIDX(c, d, b, a) + GIDX(d, c, b, a);
#undef GIDX
    out[256 + idx] = 0.125f * s;
}

// ---------------------------------------------------------------------------
// Inputs (metadata order): Z, pos, ghost, embed, W_tp, w_h, b_h, w_g, b_g.
// pos and ghost are dead code in the reference -- never touched.
// ---------------------------------------------------------------------------
extern "C" void kernel_launch(void* const* d_in, const int* in_sizes, int n_in,
                              void* d_out, int out_size) {
    const int*   Z     = (const int*)d_in[0];
    const float* embed = (const float*)d_in[3];
    const float* W_tp  = (const float*)d_in[4];
    const float* w_h   = (const float*)d_in[5];
    const float* b_h   = (const float*)d_in[6];
    const float* w_g   = (const float*)d_in[7];
    const float* b_g   = (const float*)d_in[8];
    float* out = (float*)d_out;
    const int n = in_sizes[0];

    k1<<<GRID1, 256>>>(Z, n, embed, W_tp, w_g);
    k3<<<257, 256>>>(w_g, b_g, w_h, b_h, out);
    k4<<<256, 256>>>(out);
}

// round 7
// speedup vs baseline: 1.4115x; 1.1019x over previous
#include <cuda_runtime.h>
#include <math.h>

#define H        64
#define NZ       120
#define NLAYERS  4
#define DIMH     256
#define DIMG     65536

#define TB_BLKS  120            // table blocks in k1
#define HB_BLKS  256            // histogram blocks in k1
#define PF_BLKS  512            // prefetch blocks in k1 (8 float4 each)
#define GRID1    (TB_BLKS + HB_BLKS + PF_BLKS)

// Scratch (no allocations allowed)
__device__ int   d_hist[NZ];            // global histogram (int atomics =
                                        // deterministic; k4 re-zeroes it for
                                        // the next graph replay)
__device__ float d_ftab[NZ * H];        // UNWEIGHTED post-layer table f_z
__device__ float d_gbuf[DIMG];          // unsymmetrized g
__device__ float d_sinkf;               // prefetch elision guard

// ---------------------------------------------------------------------------
// k1: three INDEPENDENT jobs in one wide launch (888 blocks = 1 wave).
//   blocks [0,120):    f_z table through 4 layers (needs embed/W_tp only)
//   blocks [120,376):  histogram of Z -> shared bins -> global int RED adds
//   blocks [376,888):  stream w_g into L2 (131072 thr x 8 float4, MLP=8)
// ---------------------------------------------------------------------------
__global__ void __launch_bounds__(256)
k1(const int* __restrict__ Z, int n,
   const float* __restrict__ embed, const float* __restrict__ W_tp,
   const float* __restrict__ w_g) {
    const int t   = threadIdx.x;
    const int bid = blockIdx.x;

    if (bid < TB_BLKS) {
        // ---- layer table (threads 0..63 active; all hit the syncs) ----
        __shared__ float xs[H];
        const int z = bid;
        if (t < H) xs[t] = embed[z * H + t];
        __syncthreads();
        #pragma unroll
        for (int l = 0; l < NLAYERS; ++l) {
            float a = 0.f;
            if (t < H) {
                const float* __restrict__ W = W_tp + l * H * H;
                #pragma unroll
                for (int k = 0; k < H; ++k)
                    a = fmaf(xs[k], W[k * H + t], a);
                a *= 0.125f;                    // INV_SQRT_H = 1/sqrt(64)
                a = a / (1.f + expf(-a));       // silu
            }
            __syncthreads();
            if (t < H) xs[t] = a;
            __syncthreads();
        }
        if (t < H) d_ftab[z * H + t] = xs[t];
    } else if (bid < TB_BLKS + HB_BLKS) {
        // ---- histogram: shared bins, then one global RED add per bin ----
        __shared__ int sh[NZ];
        const int hb = bid - TB_BLKS;
        for (int i = t; i < NZ; i += 256) sh[i] = 0;
        __syncthreads();

        // dtype sniff: Z declared int64 in the reference; with x64 off it
        // lands int32. int64 LE data (<120) has every odd word == 0.
        bool is64 = true;
        #pragma unroll
        for (int i = 0; i < 32; ++i)
            if (Z[2 * i + 1] != 0) { is64 = false; break; }

        const int4* __restrict__ Z4 = (const int4*)Z;
        const int tid = hb * 256 + t, nthr = HB_BLKS * 256;
        if (!is64) {
            const int n4 = n >> 2;
            #pragma unroll 2
            for (int i = tid; i < n4; i += nthr) {
                int4 v = Z4[i];
                atomicAdd(&sh[v.x], 1); atomicAdd(&sh[v.y], 1);
                atomicAdd(&sh[v.z], 1); atomicAdd(&sh[v.w], 1);
            }
        } else {
            const int n2 = n >> 1;              // int4 covers 2 int64 elems
            #pragma unroll 2
            for (int i = tid; i < n2; i += nthr) {
                int4 v = Z4[i];
                atomicAdd(&sh[v.x], 1); atomicAdd(&sh[v.z], 1);
            }
        }
        __syncthreads();
        // integer adds commute exactly -> deterministic counts
        for (int i = t; i < NZ; i += 256)
            if (sh[i]) atomicAdd(&d_hist[i], sh[i]);
    } else {
        // ---- w_g -> L2 prefetch: 8 independent float4 per thread ----
        const int pid = bid - TB_BLKS - HB_BLKS;        // [0,512)
        const float4* __restrict__ w4 = (const float4*)w_g;
        const int base = pid * 2048;                    // 8 chunks of 256
        float s = 0.f;
        #pragma unroll
        for (int c = 0; c < 8; ++c) {
            float4 v = __ldcg(&w4[base + c * 256 + t]);
            s += v.x + v.y + v.z + v.w;
        }
        if (s == -1.0f) d_sinkf = s;            // keeps the loads alive
    }
}

// ---------------------------------------------------------------------------
// k3 (grid 257): every block redundantly builds gf from d_hist/d_ftab
// (both tiny and L2-hot). Then blocks 0..255 compute g = gf @ w_g + b_g
// (w_g L2-resident: prefetched in k1 + persistent across replays); block 256
// does the h matvec + h symmetrization straight to out[0:256].
// ---------------------------------------------------------------------------
__global__ void __launch_bounds__(256)
k3(const float* __restrict__ w_g, const float* __restrict__ b_g,
   const float* __restrict__ w_h, const float* __restrict__ b_h,
   float* __restrict__ out) {
    __shared__ float scnt[NZ];
    __shared__ float gf[H];
    __shared__ float red[DIMH];
    const int t = threadIdx.x;

    if (t < NZ) scnt[t] = (float)d_hist[t];
    __syncthreads();

    // gf[j] = sum_z scnt[z] * f_z[j]; 4 strips of 30 z's per feature j
    {
        const int j = t & 63, p = t >> 6;
        float s = 0.f;
        #pragma unroll
        for (int z = p * 30; z < p * 30 + 30; ++z)
            s = fmaf(scnt[z], d_ftab[z * H + j], s);
        red[t] = s;
        __syncthreads();
        if (t < H) gf[t] = red[t] + red[t + 64] + red[t + 128] + red[t + 192];
        __syncthreads();
    }

    if (blockIdx.x < 256) {
        const int i = blockIdx.x * 256 + t;
        float acc = b_g[i];
        #pragma unroll
        for (int k = 0; k < H; ++k)
            acc = fmaf(gf[k], __ldcg(&w_g[k * DIMG + i]), acc);   // L2 hit
        d_gbuf[i] = acc;
    } else {
        float acc = b_h[t];
        #pragma unroll
        for (int k = 0; k < H; ++k)
            acc = fmaf(gf[k], w_h[k * DIMH + t], acc);
        red[t] = acc;
        __syncthreads();
        const int i = t >> 4, j = t & 15;
        out[t] = 0.5f * (red[i * 16 + j] + red[j * 16 + i]);
    }
}

// ---------------------------------------------------------------------------
// k4: 8-fold permutation symmetrization of g (d_gbuf is L2-hot, 256 KB).
// Block 0 also re-zeroes d_hist for the next graph replay (k3 already
// consumed it; launches are stream-ordered).
// ---------------------------------------------------------------------------
__global__ void __launch_bounds__(256)
k4(float* __restrict__ out) {
    if (blockIdx.x == 0 && threadIdx.x < NZ) d_hist[threadIdx.x] = 0;

    const int idx = blockIdx.x * 256 + threadIdx.x;
    const int a = idx >> 12, b = (idx >> 8) & 15, c = (idx >> 4) & 15, d = idx & 15;
#define GIDX(x, y, zz, w) d_gbuf[((x) << 12) | ((y) << 8) | ((zz) << 4) | (w)]
    float s = GIDX(a, b, c, d) + GIDX(b, a, c, d)
            + GIDX(a, b, d, c) + GIDX(b, a, d, c)
            + GIDX(c, d, a, b) + GIDX(d, c, a, b)
            + GIDX(c, d, b, a) + GIDX(d, c, b, a);
#undef GIDX
    out[256 + idx] = 0.125f * s;
}

// ---------------------------------------------------------------------------
// Inputs (metadata order): Z, pos, ghost, embed, W_tp, w_h, b_h, w_g, b_g.
// pos and ghost are dead code in the reference -- never touched.
// ---------------------------------------------------------------------------
extern "C" void kernel_launch(void* const* d_in, const int* in_sizes, int n_in,
                              void* d_out, int out_size) {
    const int*   Z     = (const int*)d_in[0];
    const float* embed = (const float*)d_in[3];
    const float* W_tp  = (const float*)d_in[4];
    const float* w_h   = (const float*)d_in[5];
    const float* b_h   = (const float*)d_in[6];
    const float* w_g   = (const float*)d_in[7];
    const float* b_g   = (const float*)d_in[8];
    float* out = (float*)d_out;
    const int n = in_sizes[0];

    k1<<<GRID1, 256>>>(Z, n, embed, W_tp, w_g);
    k3<<<257, 256>>>(w_g, b_g, w_h, b_h, out);
    k4<<<256, 256>>>(out);
}